// round 10
// baseline (speedup 1.0000x reference)
#include <cuda_runtime.h>
#include <cstdint>

#define E_CNT   100000
#define N_NODES 50000
#define H_CNT   4
#define D_CNT   128
#define NCAND   (3 * E_CNT)          // 300000 candidate (entry, type) pairs
#define ALPHA   0.2f
#define SCAN_B  1024
#define NTILES  ((N_NODES + SCAN_B - 1) / SCAN_B)   // 49
#define NODES_PER_BLK 8              // warp-per-node gather

// ---------------------------------------------------------------------------
// Scratch (device globals; zero-initialized at module load. Every run leaves
// g_count back at zero — scanA consumes-and-clears it — so graph replays see
// identical state).
// ---------------------------------------------------------------------------
__device__ int  g_count [N_NODES];       // candidates per node (zeroed by scanA)
__device__ int  g_off   [N_NODES + 1];   // global start offsets
__device__ int  g_cursor[N_NODES];       // fill cursors
__device__ int  g_bsum  [NTILES];        // per-tile totals
__device__ int4 g_rec   [NCAND];         // {t, n0, n1, 0} grouped by node

// ---------------------------------------------------------------------------
// Kernel 1: histogram — one thread per ENTRY e; 3 counter bumps from one
// 12-byte batch-row read. Relies on g_count == 0 on entry.
// ---------------------------------------------------------------------------
__global__ void hist_kernel(const int* __restrict__ batch) {
    int e = blockIdx.x * blockDim.x + threadIdx.x;
    if (e >= E_CNT) return;
    int b0 = batch[e * 3 + 0];
    int b1 = batch[e * 3 + 1];
    int b2 = batch[e * 3 + 2];
    atomicAdd(&g_count[b0], 1);
    atomicAdd(&g_count[b1], 1);
    atomicAdd(&g_count[b2], 1);
}

// ---------------------------------------------------------------------------
// Kernel 2 (scanA): 49 blocks x 1024. Coalesced tile load of counts, zero
// the counts, block-local exclusive scan via warp shuffles.
// ---------------------------------------------------------------------------
__global__ void __launch_bounds__(SCAN_B) scanA_kernel() {
    __shared__ int ws[32];
    const int tid = threadIdx.x;
    const int j   = blockIdx.x * SCAN_B + tid;
    const int lane = tid & 31, wid = tid >> 5;

    int c = 0;
    if (j < N_NODES) { c = g_count[j]; g_count[j] = 0; }

    int v = c;
    #pragma unroll
    for (int o = 1; o < 32; o <<= 1) {
        int t = __shfl_up_sync(0xffffffffu, v, o);
        if (lane >= o) v += t;
    }
    if (lane == 31) ws[wid] = v;
    __syncthreads();
    if (wid == 0) {
        int s = ws[lane];
        #pragma unroll
        for (int o = 1; o < 32; o <<= 1) {
            int t = __shfl_up_sync(0xffffffffu, s, o);
            if (lane >= o) s += t;
        }
        ws[lane] = s;
    }
    __syncthreads();

    int excl = v - c + (wid ? ws[wid - 1] : 0);
    if (j < N_NODES) g_off[j] = excl;
    if (tid == SCAN_B - 1) g_bsum[blockIdx.x] = excl + c;
}

// ---------------------------------------------------------------------------
// Kernel 3 (scanB): add tile prefixes (<=48 values, one warp per block),
// materialize cursors and the end sentinel.
// ---------------------------------------------------------------------------
__global__ void __launch_bounds__(SCAN_B) scanB_kernel() {
    __shared__ int s_prefix;
    const int tid = threadIdx.x;
    const int blk = blockIdx.x;

    if (tid < 32) {
        int s = 0;
        if (tid      < blk) s += g_bsum[tid];
        if (tid + 32 < blk) s += g_bsum[tid + 32];
        #pragma unroll
        for (int o = 16; o > 0; o >>= 1)
            s += __shfl_down_sync(0xffffffffu, s, o);
        if (tid == 0) s_prefix = s;
    }
    __syncthreads();
    const int prefix = s_prefix;

    int j = blk * SCAN_B + tid;
    if (j < N_NODES) {
        int off = g_off[j] + prefix;
        g_off[j]    = off;
        g_cursor[j] = off;
    }
    if (blk == 0 && tid == 0) g_off[N_NODES] = NCAND;
}

// ---------------------------------------------------------------------------
// Kernel 4: fill — one thread per ENTRY e writes all 3 records from one
// batch-row read. Order within a node is irrelevant (max over identical
// values is order-invariant -> deterministic output).
// ---------------------------------------------------------------------------
__global__ void fill_kernel(const int* __restrict__ batch) {
    int e = blockIdx.x * blockDim.x + threadIdx.x;
    if (e >= E_CNT) return;
    int b0 = batch[e * 3 + 0];
    int b1 = batch[e * 3 + 1];
    int b2 = batch[e * 3 + 2];
    int p0 = atomicAdd(&g_cursor[b0], 1);
    g_rec[p0] = make_int4(e,             b1, b2, 0);   // i=0: cols {1,2}
    int p1 = atomicAdd(&g_cursor[b1], 1);
    g_rec[p1] = make_int4(E_CNT + e,     b0, b2, 0);   // i=1: cols {0,2}
    int p2 = atomicAdd(&g_cursor[b2], 1);
    g_rec[p2] = make_int4(2 * E_CNT + e, b0, b1, 0);   // i=2: cols {0,1}
}

// ---------------------------------------------------------------------------
// FMA/MAX consumption of one candidate's already-loaded operands.
// ---------------------------------------------------------------------------
__device__ __forceinline__ void cand_fma(
    const float4 wa, const float4 wb, const float4 f0, const float4 f1,
    float4& m0, float4& m1, float4& m2, float4& m3)
{
    m0.x = fmaxf(m0.x, fmaf(wa.x, f0.x, wa.y * f1.x));
    m0.y = fmaxf(m0.y, fmaf(wa.x, f0.y, wa.y * f1.y));
    m0.z = fmaxf(m0.z, fmaf(wa.x, f0.z, wa.y * f1.z));
    m0.w = fmaxf(m0.w, fmaf(wa.x, f0.w, wa.y * f1.w));

    m1.x = fmaxf(m1.x, fmaf(wa.z, f0.x, wa.w * f1.x));
    m1.y = fmaxf(m1.y, fmaf(wa.z, f0.y, wa.w * f1.y));
    m1.z = fmaxf(m1.z, fmaf(wa.z, f0.z, wa.w * f1.z));
    m1.w = fmaxf(m1.w, fmaf(wa.z, f0.w, wa.w * f1.w));

    m2.x = fmaxf(m2.x, fmaf(wb.x, f0.x, wb.y * f1.x));
    m2.y = fmaxf(m2.y, fmaf(wb.x, f0.y, wb.y * f1.y));
    m2.z = fmaxf(m2.z, fmaf(wb.x, f0.z, wb.y * f1.z));
    m2.w = fmaxf(m2.w, fmaf(wb.x, f0.w, wb.y * f1.w));

    m3.x = fmaxf(m3.x, fmaf(wb.z, f0.x, wb.w * f1.x));
    m3.y = fmaxf(m3.y, fmaf(wb.z, f0.y, wb.w * f1.y));
    m3.z = fmaxf(m3.z, fmaf(wb.z, f0.z, wb.w * f1.z));
    m3.w = fmaxf(m3.w, fmaf(wb.z, f0.w, wb.w * f1.w));
}

// ---------------------------------------------------------------------------
// Kernel 5: gather — one warp per node. Candidate loop unrolled x4 with an
// explicit two-phase schedule: 4 records load together, then all 16 weight/
// feature float4 loads issue as one independent batch (MLP ~16), then the
// 128 FMA/MAX ops consume. Avg-6 nodes do ONE batched round-trip + tail
// instead of three. Fused residual + leaky-relu epilogue.
// ---------------------------------------------------------------------------
__global__ void __launch_bounds__(32 * NODES_PER_BLK) gather_kernel(
    const float* __restrict__ feats,   // [N, 128]
    const float* __restrict__ w,       // [3E, 4, 2]
    float*       __restrict__ out)     // [N, 4, 128]
{
    const int wid  = threadIdx.x >> 5;
    const int lane = threadIdx.x & 31;
    const int node = blockIdx.x * NODES_PER_BLK + wid;   // grid exact: 6250*8
    const int d0 = lane << 2;

    const int start = g_off[node];
    const int end   = g_off[node + 1];

    const float NI = __int_as_float(0xff800000);
    float4 m0 = make_float4(NI, NI, NI, NI);
    float4 m1 = m0, m2 = m0, m3 = m0;

    int k = start;
    for (; k + 3 < end; k += 4) {
        // phase 1: records (independent, one 16B load each)
        const int4 r0 = g_rec[k];
        const int4 r1 = g_rec[k + 1];
        const int4 r2 = g_rec[k + 2];
        const int4 r3 = g_rec[k + 3];

        // phase 2: all weight + feature loads issue together
        const float4 wa0 = *(const float4*)(w + (long)r0.x * 8);
        const float4 wb0 = *(const float4*)(w + (long)r0.x * 8 + 4);
        const float4 wa1 = *(const float4*)(w + (long)r1.x * 8);
        const float4 wb1 = *(const float4*)(w + (long)r1.x * 8 + 4);
        const float4 wa2 = *(const float4*)(w + (long)r2.x * 8);
        const float4 wb2 = *(const float4*)(w + (long)r2.x * 8 + 4);
        const float4 wa3 = *(const float4*)(w + (long)r3.x * 8);
        const float4 wb3 = *(const float4*)(w + (long)r3.x * 8 + 4);
        const float4 f00 = *(const float4*)(feats + (long)r0.y * D_CNT + d0);
        const float4 f01 = *(const float4*)(feats + (long)r0.z * D_CNT + d0);
        const float4 f10 = *(const float4*)(feats + (long)r1.y * D_CNT + d0);
        const float4 f11 = *(const float4*)(feats + (long)r1.z * D_CNT + d0);
        const float4 f20 = *(const float4*)(feats + (long)r2.y * D_CNT + d0);
        const float4 f21 = *(const float4*)(feats + (long)r2.z * D_CNT + d0);
        const float4 f30 = *(const float4*)(feats + (long)r3.y * D_CNT + d0);
        const float4 f31 = *(const float4*)(feats + (long)r3.z * D_CNT + d0);

        // phase 3: consume
        cand_fma(wa0, wb0, f00, f01, m0, m1, m2, m3);
        cand_fma(wa1, wb1, f10, f11, m0, m1, m2, m3);
        cand_fma(wa2, wb2, f20, f21, m0, m1, m2, m3);
        cand_fma(wa3, wb3, f30, f31, m0, m1, m2, m3);
    }
    for (; k < end; k++) {
        const int4 r = g_rec[k];
        const float4 wa = *(const float4*)(w + (long)r.x * 8);
        const float4 wb = *(const float4*)(w + (long)r.x * 8 + 4);
        const float4 f0 = *(const float4*)(feats + (long)r.y * D_CNT + d0);
        const float4 f1 = *(const float4*)(feats + (long)r.z * D_CNT + d0);
        cand_fma(wa, wb, f0, f1, m0, m1, m2, m3);
    }

    const float4 f = *(const float4*)(feats + (long)node * D_CNT + d0);
    float* ob = out + (long)node * (H_CNT * D_CNT) + d0;

    float4 v;
    v.x = m0.x + f.x; v.y = m0.y + f.y; v.z = m0.z + f.z; v.w = m0.w + f.w;
    v.x = (v.x >= 0.f) ? v.x : ALPHA * v.x;  v.y = (v.y >= 0.f) ? v.y : ALPHA * v.y;
    v.z = (v.z >= 0.f) ? v.z : ALPHA * v.z;  v.w = (v.w >= 0.f) ? v.w : ALPHA * v.w;
    *(float4*)(ob + 0 * D_CNT) = v;

    v.x = m1.x + f.x; v.y = m1.y + f.y; v.z = m1.z + f.z; v.w = m1.w + f.w;
    v.x = (v.x >= 0.f) ? v.x : ALPHA * v.x;  v.y = (v.y >= 0.f) ? v.y : ALPHA * v.y;
    v.z = (v.z >= 0.f) ? v.z : ALPHA * v.z;  v.w = (v.w >= 0.f) ? v.w : ALPHA * v.w;
    *(float4*)(ob + 1 * D_CNT) = v;

    v.x = m2.x + f.x; v.y = m2.y + f.y; v.z = m2.z + f.z; v.w = m2.w + f.w;
    v.x = (v.x >= 0.f) ? v.x : ALPHA * v.x;  v.y = (v.y >= 0.f) ? v.y : ALPHA * v.y;
    v.z = (v.z >= 0.f) ? v.z : ALPHA * v.z;  v.w = (v.w >= 0.f) ? v.w : ALPHA * v.w;
    *(float4*)(ob + 2 * D_CNT) = v;

    v.x = m3.x + f.x; v.y = m3.y + f.y; v.z = m3.z + f.z; v.w = m3.w + f.w;
    v.x = (v.x >= 0.f) ? v.x : ALPHA * v.x;  v.y = (v.y >= 0.f) ? v.y : ALPHA * v.y;
    v.z = (v.z >= 0.f) ? v.z : ALPHA * v.z;  v.w = (v.w >= 0.f) ? v.w : ALPHA * v.w;
    *(float4*)(ob + 3 * D_CNT) = v;
}

extern "C" void kernel_launch(void* const* d_in, const int* in_sizes, int n_in,
                              void* d_out, int out_size) {
    const int*   batch = (const int*)  d_in[0];   // [E, 3] int32
    const float* feats = (const float*)d_in[1];   // [N, 128] f32
    const float* w     = (const float*)d_in[2];   // [3E, 4, 2] f32
    float*       out   = (float*)d_out;           // [N, 512] f32

    hist_kernel <<<(E_CNT + 255) / 256, 256>>>(batch);
    scanA_kernel<<<NTILES, SCAN_B>>>();
    scanB_kernel<<<NTILES, SCAN_B>>>();
    fill_kernel <<<(E_CNT + 127) / 128, 128>>>(batch);
    gather_kernel<<<N_NODES / NODES_PER_BLK, 32 * NODES_PER_BLK>>>(feats, w, out);
}